// round 7
// baseline (speedup 1.0000x reference)
#include <cuda_runtime.h>
#include <cstdint>
#include <math_constants.h>

// Flash-attention, TF32 mma.sync, fp32 accumulate.
// Round 7: Q held in registers (loop-invariant A-fragments), BM=128 with
// 4 warps x 32 rows (keeps 2x B-fragment reuse), smem shrunk to 70.6KB ->
// 2 CTAs/SM for cross-CTA latency hiding (evidence: tensor=44%, L1=52%,
// 1 CTA/SM serialized barriers/publish).
// B=2, H=16, S=2048, DK=DV=64. Output raw reshape -> layout [B,H,S,DV].
// d_in[0]=key, d_in[1]=query, d_in[2]=value (fp32).

namespace {

constexpr int S_LEN    = 2048;
constexpr int DH       = 64;
constexpr int BM       = 128;   // query rows per CTA (32 per warp)
constexpr int BN       = 64;    // key rows per tile
constexpr int NTHREADS = 128;   // 4 warps
constexpr int NTILES   = S_LEN / BN;

// smem strides (words), conflict-free:
//  K/P stride 68: bank = 4g + j -> 32 distinct
//  V stride 72:   bank = 8j + g -> 32 distinct
constexpr int KSTR = 68;
constexpr int VSTR = 72;
constexpr int PSTR = 68;

constexpr int SMEM_WORDS = BM * PSTR + BN * KSTR + BN * VSTR;  // 17,664
constexpr int SMEM_BYTES = SMEM_WORDS * 4;                     // 70,656 -> 2 CTAs/SM

__device__ __forceinline__ uint32_t f2tf(float x) {
    uint32_t r;
    asm("cvt.rna.tf32.f32 %0, %1;" : "=r"(r) : "f"(x));
    return r;
}

__device__ __forceinline__ float fast_exp2(float x) {
    float y;
    asm("ex2.approx.ftz.f32 %0, %1;" : "=f"(y) : "f"(x));
    return y;
}

__device__ __forceinline__ void mma_tf32(float c[4],
                                         uint32_t a0, uint32_t a1,
                                         uint32_t a2, uint32_t a3,
                                         uint32_t b0, uint32_t b1) {
    asm volatile(
        "mma.sync.aligned.m16n8k8.row.col.f32.tf32.tf32.f32 "
        "{%0,%1,%2,%3}, {%4,%5,%6,%7}, {%8,%9}, {%0,%1,%2,%3};"
        : "+f"(c[0]), "+f"(c[1]), "+f"(c[2]), "+f"(c[3])
        : "r"(a0), "r"(a1), "r"(a2), "r"(a3), "r"(b0), "r"(b1));
}

}  // namespace

__global__ __launch_bounds__(NTHREADS, 2)
void mha_fa_tf32(const float* __restrict__ Kg,
                 const float* __restrict__ Qg,
                 const float* __restrict__ Vg,
                 float* __restrict__ Out) {
    extern __shared__ uint32_t smem[];
    uint32_t* sP = smem;                 // also Q staging scratch at startup
    uint32_t* sK = sP + BM * PSTR;
    uint32_t* sV = sK + BN * KSTR;

    const int tid   = threadIdx.x;
    const int warp  = tid >> 5;
    const int lane  = tid & 31;
    const int g     = lane >> 2;   // group id 0..7
    const int j     = lane & 3;    // quad id  0..3
    const int mbase = warp * 32;   // this warp's 32 query rows

    const int bh = blockIdx.y;     // b*16 + h
    const int qt = blockIdx.x;     // query tile

    const size_t head_base = (size_t)bh * S_LEN * DH;
    const float* Qp = Qg + head_base + (size_t)qt * BM * DH;
    const float* Kp = Kg + head_base;
    const float* Vp = Vg + head_base;

    // ---- stage Q through sP (scaled by 0.125, tf32), then pull A-frags to regs ----
    for (int i = tid * 4; i < BM * DH; i += NTHREADS * 4) {
        float4 v = *reinterpret_cast<const float4*>(Qp + i);
        uint4 w;
        w.x = f2tf(v.x * 0.125f);
        w.y = f2tf(v.y * 0.125f);
        w.z = f2tf(v.z * 0.125f);
        w.w = f2tf(v.w * 0.125f);
        *reinterpret_cast<uint4*>(sP + (i >> 6) * PSTR + (i & 63)) = w;
    }
    __syncthreads();

    uint32_t q[2][8][4];   // loop-invariant Q A-fragments (64 regs)
    #pragma unroll
    for (int m2 = 0; m2 < 2; ++m2) {
        const int r0 = mbase + m2 * 16 + g;
        #pragma unroll
        for (int kk = 0; kk < 8; ++kk) {
            q[m2][kk][0] = sP[(r0    ) * PSTR + kk * 8 + j];
            q[m2][kk][1] = sP[(r0 + 8) * PSTR + kk * 8 + j];
            q[m2][kk][2] = sP[(r0    ) * PSTR + kk * 8 + j + 4];
            q[m2][kk][3] = sP[(r0 + 8) * PSTR + kk * 8 + j + 4];
        }
    }
    // (no barrier needed: first P write happens after the loop-top barriers)

    float o[2][8][4];
    #pragma unroll
    for (int m2 = 0; m2 < 2; ++m2)
        #pragma unroll
        for (int n = 0; n < 8; ++n)
            #pragma unroll
            for (int t = 0; t < 4; ++t) o[m2][n][t] = 0.f;

    float mrow[2][2] = {{-CUDART_INF_F, -CUDART_INF_F},
                        {-CUDART_INF_F, -CUDART_INF_F}};
    float lrow[2][2] = {{0.f, 0.f}, {0.f, 0.f}};
    const float L2E = 1.4426950408889634f;

    for (int kt = 0; kt < NTILES; ++kt) {
        __syncthreads();  // previous tile's smem fully consumed

        // ---- publish K/V tile (gmem -> cvt tf32 -> smem); L2-resident,
        //      latency hidden by the co-resident CTA ----
        const float* Kt = Kp + kt * BN * DH;
        const float* Vt = Vp + kt * BN * DH;
        for (int i = tid * 4; i < BN * DH; i += NTHREADS * 4) {
            const int r = i >> 6, c = i & 63;
            float4 kv = *reinterpret_cast<const float4*>(Kt + i);
            uint4 wk;
            wk.x = f2tf(kv.x); wk.y = f2tf(kv.y);
            wk.z = f2tf(kv.z); wk.w = f2tf(kv.w);
            *reinterpret_cast<uint4*>(sK + r * KSTR + c) = wk;
            float4 vv = *reinterpret_cast<const float4*>(Vt + i);
            uint4 wv;
            wv.x = f2tf(vv.x); wv.y = f2tf(vv.y);
            wv.z = f2tf(vv.z); wv.w = f2tf(vv.w);
            *reinterpret_cast<uint4*>(sV + r * VSTR + c) = wv;
        }
        __syncthreads();

        // ---- S = (Q*scale) @ K^T : 32x64 per warp; Q from regs, K frags 2x reused ----
        float c2[2][8][4];
        #pragma unroll
        for (int m2 = 0; m2 < 2; ++m2)
            #pragma unroll
            for (int n = 0; n < 8; ++n)
                #pragma unroll
                for (int t = 0; t < 4; ++t) c2[m2][n][t] = 0.f;

        #pragma unroll
        for (int kk = 0; kk < 8; ++kk) {
            const int k0 = kk * 8;
            #pragma unroll
            for (int n = 0; n < 8; ++n) {
                const uint32_t b0 = sK[(n * 8 + g) * KSTR + k0 + j];
                const uint32_t b1 = sK[(n * 8 + g) * KSTR + k0 + j + 4];
                #pragma unroll
                for (int m2 = 0; m2 < 2; ++m2)
                    mma_tf32(c2[m2][n], q[m2][kk][0], q[m2][kk][1],
                             q[m2][kk][2], q[m2][kk][3], b0, b1);
            }
        }

        // ---- online softmax, per m-fragment ----
        #pragma unroll
        for (int m2 = 0; m2 < 2; ++m2) {
            float mx0 = mrow[m2][0], mx1 = mrow[m2][1];
            #pragma unroll
            for (int n = 0; n < 8; ++n) {
                mx0 = fmaxf(mx0, fmaxf(c2[m2][n][0], c2[m2][n][1]));
                mx1 = fmaxf(mx1, fmaxf(c2[m2][n][2], c2[m2][n][3]));
            }
            mx0 = fmaxf(mx0, __shfl_xor_sync(0xffffffffu, mx0, 1));
            mx0 = fmaxf(mx0, __shfl_xor_sync(0xffffffffu, mx0, 2));
            mx1 = fmaxf(mx1, __shfl_xor_sync(0xffffffffu, mx1, 1));
            mx1 = fmaxf(mx1, __shfl_xor_sync(0xffffffffu, mx1, 2));

            const float sc0 = fast_exp2((mrow[m2][0] - mx0) * L2E);
            const float sc1 = fast_exp2((mrow[m2][1] - mx1) * L2E);
            mrow[m2][0] = mx0; mrow[m2][1] = mx1;

            const int r0 = mbase + m2 * 16 + g;
            float s0 = 0.f, s1 = 0.f;
            #pragma unroll
            for (int n = 0; n < 8; ++n) {
                const float p0 = fast_exp2((c2[m2][n][0] - mx0) * L2E);
                const float p1 = fast_exp2((c2[m2][n][1] - mx0) * L2E);
                const float p2 = fast_exp2((c2[m2][n][2] - mx1) * L2E);
                const float p3 = fast_exp2((c2[m2][n][3] - mx1) * L2E);
                s0 += p0 + p1;
                s1 += p2 + p3;
                sP[(r0    ) * PSTR + n * 8 + 2 * j    ] = f2tf(p0);
                sP[(r0    ) * PSTR + n * 8 + 2 * j + 1] = f2tf(p1);
                sP[(r0 + 8) * PSTR + n * 8 + 2 * j    ] = f2tf(p2);
                sP[(r0 + 8) * PSTR + n * 8 + 2 * j + 1] = f2tf(p3);
            }
            s0 += __shfl_xor_sync(0xffffffffu, s0, 1);
            s0 += __shfl_xor_sync(0xffffffffu, s0, 2);
            s1 += __shfl_xor_sync(0xffffffffu, s1, 1);
            s1 += __shfl_xor_sync(0xffffffffu, s1, 2);
            lrow[m2][0] = lrow[m2][0] * sc0 + s0;
            lrow[m2][1] = lrow[m2][1] * sc1 + s1;

            #pragma unroll
            for (int n = 0; n < 8; ++n) {
                o[m2][n][0] *= sc0; o[m2][n][1] *= sc0;
                o[m2][n][2] *= sc1; o[m2][n][3] *= sc1;
            }
        }

        __syncwarp();  // sP rows are warp-private

        // ---- O += P @ V : 32x64 per warp, V frags reused 2x ----
        #pragma unroll
        for (int k0 = 0; k0 < BN; k0 += 8) {
            uint32_t a[2][4];
            #pragma unroll
            for (int m2 = 0; m2 < 2; ++m2) {
                const int r0 = mbase + m2 * 16 + g;
                a[m2][0] = sP[(r0    ) * PSTR + k0 + j];
                a[m2][1] = sP[(r0 + 8) * PSTR + k0 + j];
                a[m2][2] = sP[(r0    ) * PSTR + k0 + j + 4];
                a[m2][3] = sP[(r0 + 8) * PSTR + k0 + j + 4];
            }
            #pragma unroll
            for (int n = 0; n < 8; ++n) {
                const uint32_t b0 = sV[(k0 + j    ) * VSTR + n * 8 + g];
                const uint32_t b1 = sV[(k0 + j + 4) * VSTR + n * 8 + g];
                #pragma unroll
                for (int m2 = 0; m2 < 2; ++m2)
                    mma_tf32(o[m2][n], a[m2][0], a[m2][1], a[m2][2], a[m2][3],
                             b0, b1);
            }
        }
    }

    // ---- epilogue: normalize + store (output layout = contiguous [B,H,S,DV]) ----
    #pragma unroll
    for (int m2 = 0; m2 < 2; ++m2) {
        const float inv0 = 1.0f / lrow[m2][0];
        const float inv1 = 1.0f / lrow[m2][1];
        float* out0 = Out + head_base
                    + (size_t)(qt * BM + mbase + m2 * 16 + g) * DH;
        float* out1 = out0 + 8 * DH;
        #pragma unroll
        for (int n = 0; n < 8; ++n) {
            float2 v0 = make_float2(o[m2][n][0] * inv0, o[m2][n][1] * inv0);
            *reinterpret_cast<float2*>(out0 + n * 8 + 2 * j) = v0;
            float2 v1 = make_float2(o[m2][n][2] * inv1, o[m2][n][3] * inv1);
            *reinterpret_cast<float2*>(out1 + n * 8 + 2 * j) = v1;
        }
    }
}

extern "C" void kernel_launch(void* const* d_in, const int* in_sizes, int n_in,
                              void* d_out, int out_size) {
    const float* K = (const float*)d_in[0];
    const float* Q = (const float*)d_in[1];
    const float* V = (const float*)d_in[2];
    float* O = (float*)d_out;

    cudaFuncSetAttribute(mha_fa_tf32,
                         cudaFuncAttributeMaxDynamicSharedMemorySize,
                         SMEM_BYTES);

    dim3 grid(S_LEN / BM, 32);  // 16 query tiles x 32 (b,h) heads = 512 CTAs
    mha_fa_tf32<<<grid, NTHREADS, SMEM_BYTES>>>(K, Q, V, O);
}